// round 6
// baseline (speedup 1.0000x reference)
#include <cuda_runtime.h>
#include <cuda_bf16.h>

#define N_NODES 100000
#define N_EDGES 640000
#define D 128

// ---------------- scratch (static device globals; no allocations) ----------
__device__ __align__(16) float g_agg[(size_t)N_NODES * D];   // 51.2 MB
__device__ __align__(16) float g_h[(size_t)N_NODES * D];     // 51.2 MB
__device__ int   g_cnt[N_NODES];
__device__ float g_rcnt[N_NODES];

// ---------------- small utility kernels ------------------------------------
__global__ void zero_agg_kernel() {
    size_t i = (size_t)blockIdx.x * blockDim.x + threadIdx.x;
    size_t n4 = (size_t)N_NODES * D / 4;
    float4* p = reinterpret_cast<float4*>(g_agg);
    for (; i < n4; i += (size_t)gridDim.x * blockDim.x)
        p[i] = make_float4(0.f, 0.f, 0.f, 0.f);
}

__global__ void zero_cnt_kernel() {
    int i = blockIdx.x * blockDim.x + threadIdx.x;
    if (i < N_NODES) g_cnt[i] = 0;
}

// edge_index is int32 (JAX x64 disabled downgrades int64 -> int32)
__global__ void count_kernel(const int* __restrict__ ei) {
    int e = blockIdx.x * blockDim.x + threadIdx.x;
    if (e < N_EDGES) {
        int d = ei[N_EDGES + e];
        atomicAdd(&g_cnt[d], 1);
    }
}

__global__ void rcnt_kernel() {
    int i = blockIdx.x * blockDim.x + threadIdx.x;
    if (i < N_NODES) g_rcnt[i] = 1.0f / fmaxf((float)g_cnt[i], 1.0f);
}

// ---------------- scatter: one warp per edge, scalar atomic adds -----------
template <bool FROM_GH>
__global__ void scatter_kernel(const float* __restrict__ xin,
                               const int* __restrict__ ei) {
    int w    = (blockIdx.x * blockDim.x + threadIdx.x) >> 5;
    int lane = threadIdx.x & 31;
    if (w >= N_EDGES) return;
    const float* x = FROM_GH ? g_h : xin;
    int s = ei[w];
    int d = ei[N_EDGES + w];
    const float4 v = *reinterpret_cast<const float4*>(x + (size_t)s * D + lane * 4);
    float* p = g_agg + (size_t)d * D + lane * 4;
    atomicAdd(p + 0, v.x);
    atomicAdd(p + 1, v.y);
    atomicAdd(p + 2, v.z);
    atomicAdd(p + 3, v.w);
}

// ---------------- fused GEMM + bias + row L2-norm (+ReLU) ------------------
// out[n][j] = norm_row( mean_agg[n] @ Wl^T + bl + xin[n] @ Wr^T )
// Tile: 128 nodes x 128 outputs, K = 256 (agg half then x half), BK = 16.
// 256 threads, 8x8 microtile each. Mean (rcnt scale) folded into A load.
constexpr int BM = 128;
constexpr int BK = 16;
constexpr int TM = 8;
constexpr int TN = 8;

template <bool RELU, bool GH_IN, bool GH_OUT>
__global__ __launch_bounds__(256, 2)
void gemm_norm_kernel(const float* __restrict__ xin_arg,
                      const float* __restrict__ Wl,
                      const float* __restrict__ bl,
                      const float* __restrict__ Wr,
                      float* __restrict__ out_arg) {
    __shared__ float As[BM][BK + 4];   // [128][20]
    __shared__ float Bs[BK][D + 4];    // [16][132]

    const float* xin = GH_IN  ? g_h : xin_arg;
    float*       out = GH_OUT ? g_h : out_arg;

    const int tid = threadIdx.x;
    const int tx  = tid & 15;          // output-column group (j = tx*8 + jj)
    const int ty  = tid >> 4;          // node-row group    (n = ty*8 + i)
    const int n0  = blockIdx.x * BM;

    float c[TM][TN];
#pragma unroll
    for (int i = 0; i < TM; ++i)
#pragma unroll
        for (int j = 0; j < TN; ++j) c[i][j] = 0.f;

#pragma unroll 1
    for (int kt = 0; kt < 16; ++kt) {
        const bool useAgg = (kt < 8);
        const float* Asrc = useAgg ? g_agg : xin;
        const float* Wsrc = useAgg ? Wl : Wr;
        const int gk0 = (kt & 7) * BK;   // local K offset 0..112

        // Load A tile: 128 rows x 16 cols = 512 float4, 2 per thread.
#pragma unroll
        for (int l = 0; l < 2; ++l) {
            int lin = tid + l * 256;          // 0..511
            int row = lin >> 2;               // 0..127
            int c4  = lin & 3;                // 0..3
            int n   = n0 + row;
            int ncl = n < N_NODES ? n : (N_NODES - 1);
            float4 v = *reinterpret_cast<const float4*>(
                Asrc + (size_t)ncl * D + gk0 + c4 * 4);
            if (useAgg) {
                float s = g_rcnt[ncl];
                v.x *= s; v.y *= s; v.z *= s; v.w *= s;
            }
            *reinterpret_cast<float4*>(&As[row][c4 * 4]) = v;
        }
        // Load B tile (transposed): Bs[k][j] = Wsrc[j][gk0+k].
#pragma unroll
        for (int l = 0; l < 2; ++l) {
            int lin = tid + l * 256;
            int j   = lin >> 2;
            int c4  = lin & 3;
            float4 w = *reinterpret_cast<const float4*>(
                Wsrc + j * D + gk0 + c4 * 4);
            Bs[c4 * 4 + 0][j] = w.x;
            Bs[c4 * 4 + 1][j] = w.y;
            Bs[c4 * 4 + 2][j] = w.z;
            Bs[c4 * 4 + 3][j] = w.w;
        }
        __syncthreads();

#pragma unroll
        for (int k = 0; k < BK; ++k) {
            float a[TM], b[TN];
#pragma unroll
            for (int i = 0; i < TM; ++i) a[i] = As[ty * TM + i][k];
            *reinterpret_cast<float4*>(&b[0]) =
                *reinterpret_cast<const float4*>(&Bs[k][tx * TN]);
            *reinterpret_cast<float4*>(&b[4]) =
                *reinterpret_cast<const float4*>(&Bs[k][tx * TN + 4]);
#pragma unroll
            for (int i = 0; i < TM; ++i)
#pragma unroll
                for (int j = 0; j < TN; ++j) c[i][j] += a[i] * b[j];
        }
        __syncthreads();
    }

    // ---- epilogue: bias, row sum-of-squares (shfl over 16 owners), store --
    float bias[TN];
    *reinterpret_cast<float4*>(&bias[0]) =
        *reinterpret_cast<const float4*>(bl + tx * TN);
    *reinterpret_cast<float4*>(&bias[4]) =
        *reinterpret_cast<const float4*>(bl + tx * TN + 4);

    float ss[TM];
#pragma unroll
    for (int i = 0; i < TM; ++i) {
        float s = 0.f;
#pragma unroll
        for (int j = 0; j < TN; ++j) {
            c[i][j] += bias[j];
            s += c[i][j] * c[i][j];
        }
        ss[i] = s;
    }
    // The 16 threads owning one row (tx = 0..15) are lanes L..L+15 of one
    // warp: XOR-shuffles with masks 1,2,4,8 reduce within that group.
#pragma unroll
    for (int m = 1; m < 16; m <<= 1)
#pragma unroll
        for (int i = 0; i < TM; ++i)
            ss[i] += __shfl_xor_sync(0xffffffffu, ss[i], m);

#pragma unroll
    for (int i = 0; i < TM; ++i) {
        int n = n0 + ty * TM + i;
        if (n >= N_NODES) continue;
        float inv = 1.0f / fmaxf(sqrtf(ss[i]), 1e-12f);
        float4 o0, o1;
        o0.x = c[i][0] * inv; o0.y = c[i][1] * inv;
        o0.z = c[i][2] * inv; o0.w = c[i][3] * inv;
        o1.x = c[i][4] * inv; o1.y = c[i][5] * inv;
        o1.z = c[i][6] * inv; o1.w = c[i][7] * inv;
        if (RELU) {
            o0.x = fmaxf(o0.x, 0.f); o0.y = fmaxf(o0.y, 0.f);
            o0.z = fmaxf(o0.z, 0.f); o0.w = fmaxf(o0.w, 0.f);
            o1.x = fmaxf(o1.x, 0.f); o1.y = fmaxf(o1.y, 0.f);
            o1.z = fmaxf(o1.z, 0.f); o1.w = fmaxf(o1.w, 0.f);
        }
        *reinterpret_cast<float4*>(out + (size_t)n * D + tx * TN)     = o0;
        *reinterpret_cast<float4*>(out + (size_t)n * D + tx * TN + 4) = o1;
    }
}

// ---------------- launch ----------------------------------------------------
extern "C" void kernel_launch(void* const* d_in, const int* in_sizes, int n_in,
                              void* d_out, int out_size) {
    const float* x   = (const float*)d_in[0];
    const int*   ei  = (const int*)d_in[1];     // int32! (JAX x64 disabled)
    const float* Wl1 = (const float*)d_in[2];
    const float* bl1 = (const float*)d_in[3];
    const float* Wr1 = (const float*)d_in[4];
    const float* Wl2 = (const float*)d_in[5];
    const float* bl2 = (const float*)d_in[6];
    const float* Wr2 = (const float*)d_in[7];
    float* out = (float*)d_out;

    const int zblocks = 12500;                         // 3.2M float4, grid-stride
    const int eblocks = (N_EDGES + 255) / 256;         // 2500
    const int nblocks = (N_NODES + 255) / 256;         // 391
    const int sblocks = (N_EDGES * 32 + 255) / 256;    // 80000 (warp/edge)
    const int gblocks = (N_NODES + BM - 1) / BM;       // 782

    // Degree counts (edge structure is layer-invariant): once.
    zero_cnt_kernel<<<nblocks, 256>>>();
    count_kernel<<<eblocks, 256>>>(ei);
    rcnt_kernel<<<nblocks, 256>>>();

    // Layer 1: agg(x) -> gemm -> g_h (with ReLU)
    zero_agg_kernel<<<zblocks, 256>>>();
    scatter_kernel<false><<<sblocks, 256>>>(x, ei);
    gemm_norm_kernel<true, false, true><<<gblocks, 256>>>(x, Wl1, bl1, Wr1, nullptr);

    // Layer 2: agg(g_h) -> gemm -> out
    zero_agg_kernel<<<zblocks, 256>>>();
    scatter_kernel<true><<<sblocks, 256>>>(nullptr, ei);
    gemm_norm_kernel<false, true, false><<<gblocks, 256>>>(nullptr, Wl2, bl2, Wr2, out);
}

// round 8
// speedup vs baseline: 1.5914x; 1.5914x over previous
#include <cuda_runtime.h>
#include <cuda_bf16.h>

#define N_NODES 100000
#define N_EDGES 640000
#define D 128
#define NB 391   // ceil(N_NODES/256)

// ---------------- scratch (static device globals; no allocations) ----------
__device__ __align__(16) float g_agg[(size_t)N_NODES * D];   // 51.2 MB
__device__ __align__(16) float g_h[(size_t)N_NODES * D];     // 51.2 MB
__device__ int   g_cnt[N_NODES];
__device__ float g_rcnt[N_NODES];
__device__ int   g_rowptr[N_NODES];
__device__ int   g_excl[N_NODES];
__device__ int   g_cursor[N_NODES];
__device__ int   g_srcs[N_EDGES];
__device__ int   g_bsum[512];
__device__ int   g_boff[512];

// ---------------- degree count ---------------------------------------------
__global__ void zero_cnt_kernel() {
    int i = blockIdx.x * blockDim.x + threadIdx.x;
    if (i < N_NODES) g_cnt[i] = 0;
}

// edge_index is int32 (JAX x64 disabled downgrades int64 -> int32)
__global__ void count_kernel(const int* __restrict__ ei) {
    int e = blockIdx.x * blockDim.x + threadIdx.x;
    if (e < N_EDGES) atomicAdd(&g_cnt[ei[N_EDGES + e]], 1);
}

__global__ void rcnt_kernel() {
    int i = blockIdx.x * blockDim.x + threadIdx.x;
    if (i < N_NODES) g_rcnt[i] = 1.0f / fmaxf((float)g_cnt[i], 1.0f);
}

// ---------------- 3-kernel exclusive scan of g_cnt -> g_rowptr -------------
__global__ void scan_local_kernel() {      // NB blocks x 256
    __shared__ int s[256];
    int i = blockIdx.x * 256 + threadIdx.x;
    int v = (i < N_NODES) ? g_cnt[i] : 0;
    s[threadIdx.x] = v;
    __syncthreads();
#pragma unroll
    for (int off = 1; off < 256; off <<= 1) {
        int t = (threadIdx.x >= off) ? s[threadIdx.x - off] : 0;
        __syncthreads();
        s[threadIdx.x] += t;
        __syncthreads();
    }
    if (i < N_NODES) g_excl[i] = s[threadIdx.x] - v;   // block-local exclusive
    if (threadIdx.x == 255) g_bsum[blockIdx.x] = s[255];
}

__global__ void scan_bsums_kernel() {      // 1 block x 512
    __shared__ int s[512];
    int v = (threadIdx.x < NB) ? g_bsum[threadIdx.x] : 0;
    s[threadIdx.x] = v;
    __syncthreads();
#pragma unroll
    for (int off = 1; off < 512; off <<= 1) {
        int t = (threadIdx.x >= off) ? s[threadIdx.x - off] : 0;
        __syncthreads();
        s[threadIdx.x] += t;
        __syncthreads();
    }
    if (threadIdx.x < NB) g_boff[threadIdx.x] = s[threadIdx.x] - v;
}

__global__ void scan_add_kernel() {        // NB blocks x 256
    int i = blockIdx.x * 256 + threadIdx.x;
    if (i < N_NODES) {
        int r = g_excl[i] + g_boff[blockIdx.x];
        g_rowptr[i] = r;
        g_cursor[i] = r;
    }
}

__global__ void fill_src_kernel(const int* __restrict__ ei) {
    int e = blockIdx.x * blockDim.x + threadIdx.x;
    if (e < N_EDGES) {
        int d = ei[N_EDGES + e];
        int pos = atomicAdd(&g_cursor[d], 1);
        g_srcs[pos] = ei[e];
    }
}

// ---------------- aggregation: warp-per-node CSR gather (mean) -------------
template <bool FROM_GH>
__global__ __launch_bounds__(256)
void agg_kernel(const float* __restrict__ xin) {
    int node = blockIdx.x * 8 + (threadIdx.x >> 5);
    int lane = threadIdx.x & 31;
    if (node >= N_NODES) return;
    const float* x = FROM_GH ? g_h : xin;
    int beg = g_rowptr[node];
    int end = beg + g_cnt[node];

    float4 acc = make_float4(0.f, 0.f, 0.f, 0.f);
    int p = beg;
    for (; p + 1 < end; p += 2) {
        int s0 = g_srcs[p];
        int s1 = g_srcs[p + 1];
        float4 v0 = *reinterpret_cast<const float4*>(x + (size_t)s0 * D + lane * 4);
        float4 v1 = *reinterpret_cast<const float4*>(x + (size_t)s1 * D + lane * 4);
        acc.x += v0.x; acc.y += v0.y; acc.z += v0.z; acc.w += v0.w;
        acc.x += v1.x; acc.y += v1.y; acc.z += v1.z; acc.w += v1.w;
    }
    if (p < end) {
        int s0 = g_srcs[p];
        float4 v0 = *reinterpret_cast<const float4*>(x + (size_t)s0 * D + lane * 4);
        acc.x += v0.x; acc.y += v0.y; acc.z += v0.z; acc.w += v0.w;
    }
    float r = g_rcnt[node];
    acc.x *= r; acc.y *= r; acc.z *= r; acc.w *= r;
    *reinterpret_cast<float4*>(g_agg + (size_t)node * D + lane * 4) = acc;
}

// ---------------- fused GEMM + bias + row L2-norm (+ReLU) ------------------
// out[n][j] = norm_row( g_agg[n] @ Wl^T + bl + xin[n] @ Wr^T )
constexpr int BM = 128;
constexpr int BK = 16;
constexpr int TM = 8;
constexpr int TN = 8;

template <bool RELU, bool GH_IN, bool GH_OUT>
__global__ __launch_bounds__(256, 2)
void gemm_norm_kernel(const float* __restrict__ xin_arg,
                      const float* __restrict__ Wl,
                      const float* __restrict__ bl,
                      const float* __restrict__ Wr,
                      float* __restrict__ out_arg) {
    __shared__ float As[BM][BK + 4];   // [128][20]
    __shared__ float Bs[BK][D + 4];    // [16][132]

    const float* xin = GH_IN  ? g_h : xin_arg;
    float*       out = GH_OUT ? g_h : out_arg;

    const int tid = threadIdx.x;
    const int tx  = tid & 15;          // output-column group (j = tx*8 + jj)
    const int ty  = tid >> 4;          // node-row group    (n = ty*8 + i)
    const int n0  = blockIdx.x * BM;

    float c[TM][TN];
#pragma unroll
    for (int i = 0; i < TM; ++i)
#pragma unroll
        for (int j = 0; j < TN; ++j) c[i][j] = 0.f;

#pragma unroll 1
    for (int kt = 0; kt < 16; ++kt) {
        const bool useAgg = (kt < 8);
        const float* Asrc = useAgg ? g_agg : xin;
        const float* Wsrc = useAgg ? Wl : Wr;
        const int gk0 = (kt & 7) * BK;   // local K offset 0..112

        // Load A tile: 128 rows x 16 cols = 512 float4, 2 per thread.
#pragma unroll
        for (int l = 0; l < 2; ++l) {
            int lin = tid + l * 256;          // 0..511
            int row = lin >> 2;               // 0..127
            int c4  = lin & 3;                // 0..3
            int n   = n0 + row;
            int ncl = n < N_NODES ? n : (N_NODES - 1);
            float4 v = *reinterpret_cast<const float4*>(
                Asrc + (size_t)ncl * D + gk0 + c4 * 4);
            *reinterpret_cast<float4*>(&As[row][c4 * 4]) = v;
        }
        // Load B tile (transposed): Bs[k][j] = Wsrc[j][gk0+k].
#pragma unroll
        for (int l = 0; l < 2; ++l) {
            int lin = tid + l * 256;
            int j   = lin >> 2;
            int c4  = lin & 3;
            float4 w = *reinterpret_cast<const float4*>(
                Wsrc + j * D + gk0 + c4 * 4);
            Bs[c4 * 4 + 0][j] = w.x;
            Bs[c4 * 4 + 1][j] = w.y;
            Bs[c4 * 4 + 2][j] = w.z;
            Bs[c4 * 4 + 3][j] = w.w;
        }
        __syncthreads();

#pragma unroll
        for (int k = 0; k < BK; ++k) {
            float a[TM], b[TN];
#pragma unroll
            for (int i = 0; i < TM; ++i) a[i] = As[ty * TM + i][k];
            *reinterpret_cast<float4*>(&b[0]) =
                *reinterpret_cast<const float4*>(&Bs[k][tx * TN]);
            *reinterpret_cast<float4*>(&b[4]) =
                *reinterpret_cast<const float4*>(&Bs[k][tx * TN + 4]);
#pragma unroll
            for (int i = 0; i < TM; ++i)
#pragma unroll
                for (int j = 0; j < TN; ++j) c[i][j] += a[i] * b[j];
        }
        __syncthreads();
    }

    // ---- epilogue: bias, row sum-of-squares (shfl over 16 owners), store --
    float bias[TN];
    *reinterpret_cast<float4*>(&bias[0]) =
        *reinterpret_cast<const float4*>(bl + tx * TN);
    *reinterpret_cast<float4*>(&bias[4]) =
        *reinterpret_cast<const float4*>(bl + tx * TN + 4);

    float ss[TM];
#pragma unroll
    for (int i = 0; i < TM; ++i) {
        float s = 0.f;
#pragma unroll
        for (int j = 0; j < TN; ++j) {
            c[i][j] += bias[j];
            s += c[i][j] * c[i][j];
        }
        ss[i] = s;
    }
    // The 16 threads owning one row (tx = 0..15) share a 16-lane half-warp.
#pragma unroll
    for (int m = 1; m < 16; m <<= 1)
#pragma unroll
        for (int i = 0; i < TM; ++i)
            ss[i] += __shfl_xor_sync(0xffffffffu, ss[i], m);

#pragma unroll
    for (int i = 0; i < TM; ++i) {
        int n = n0 + ty * TM + i;
        if (n >= N_NODES) continue;
        float inv = 1.0f / fmaxf(sqrtf(ss[i]), 1e-12f);
        float4 o0, o1;
        o0.x = c[i][0] * inv; o0.y = c[i][1] * inv;
        o0.z = c[i][2] * inv; o0.w = c[i][3] * inv;
        o1.x = c[i][4] * inv; o1.y = c[i][5] * inv;
        o1.z = c[i][6] * inv; o1.w = c[i][7] * inv;
        if (RELU) {
            o0.x = fmaxf(o0.x, 0.f); o0.y = fmaxf(o0.y, 0.f);
            o0.z = fmaxf(o0.z, 0.f); o0.w = fmaxf(o0.w, 0.f);
            o1.x = fmaxf(o1.x, 0.f); o1.y = fmaxf(o1.y, 0.f);
            o1.z = fmaxf(o1.z, 0.f); o1.w = fmaxf(o1.w, 0.f);
        }
        *reinterpret_cast<float4*>(out + (size_t)n * D + tx * TN)     = o0;
        *reinterpret_cast<float4*>(out + (size_t)n * D + tx * TN + 4) = o1;
    }
}

// ---------------- launch ----------------------------------------------------
extern "C" void kernel_launch(void* const* d_in, const int* in_sizes, int n_in,
                              void* d_out, int out_size) {
    const float* x   = (const float*)d_in[0];
    const int*   ei  = (const int*)d_in[1];     // int32
    const float* Wl1 = (const float*)d_in[2];
    const float* bl1 = (const float*)d_in[3];
    const float* Wr1 = (const float*)d_in[4];
    const float* Wl2 = (const float*)d_in[5];
    const float* bl2 = (const float*)d_in[6];
    const float* Wr2 = (const float*)d_in[7];
    float* out = (float*)d_out;

    const int eblocks = (N_EDGES + 255) / 256;         // 2500
    const int ablocks = (N_NODES + 7) / 8;             // 12500 (warp/node)
    const int gblocks = (N_NODES + BM - 1) / BM;       // 782

    // CSR build (edge structure is layer-invariant): once per call.
    zero_cnt_kernel<<<NB, 256>>>();
    count_kernel<<<eblocks, 256>>>(ei);
    rcnt_kernel<<<NB, 256>>>();
    scan_local_kernel<<<NB, 256>>>();
    scan_bsums_kernel<<<1, 512>>>();
    scan_add_kernel<<<NB, 256>>>();
    fill_src_kernel<<<eblocks, 256>>>(ei);

    // Layer 1: agg(x) -> gemm -> g_h (with ReLU)
    agg_kernel<false><<<ablocks, 256>>>(x);
    gemm_norm_kernel<true, false, true><<<gblocks, 256>>>(x, Wl1, bl1, Wr1, nullptr);

    // Layer 2: agg(g_h) -> gemm -> out
    agg_kernel<true><<<ablocks, 256>>>(nullptr);
    gemm_norm_kernel<false, true, false><<<gblocks, 256>>>(nullptr, Wl2, bl2, Wr2, out);
}

// round 11
// speedup vs baseline: 2.4846x; 1.5613x over previous
#include <cuda_runtime.h>
#include <cuda_bf16.h>
#include <cstdint>

#define N_NODES 100000
#define N_EDGES 640000
#define D 128
#define NB 391   // ceil(N_NODES/256)

// ======================= PTX helpers ========================================
__device__ __forceinline__ uint32_t smem_u32(const void* p) {
    uint32_t a;
    asm("{ .reg .u64 t; cvta.to.shared.u64 t, %1; cvt.u32.u64 %0, t; }"
        : "=r"(a) : "l"(p));
    return a;
}
#define LDSM_X4(r0, r1, r2, r3, addr) \
    asm volatile("ldmatrix.sync.aligned.m8n8.x4.shared.b16 {%0,%1,%2,%3}, [%4];" \
        : "=r"(r0), "=r"(r1), "=r"(r2), "=r"(r3) : "r"(addr))
#define LDSM_X2(r0, r1, addr) \
    asm volatile("ldmatrix.sync.aligned.m8n8.x2.shared.b16 {%0,%1}, [%2];" \
        : "=r"(r0), "=r"(r1) : "r"(addr))
#define MMA_BF16(c, a, b0, b1) \
    asm volatile("mma.sync.aligned.m16n8k16.row.col.f32.bf16.bf16.f32 " \
        "{%0,%1,%2,%3},{%4,%5,%6,%7},{%8,%9},{%0,%1,%2,%3};" \
        : "+f"((c)[0]), "+f"((c)[1]), "+f"((c)[2]), "+f"((c)[3]) \
        : "r"((a)[0]), "r"((a)[1]), "r"((a)[2]), "r"((a)[3]), "r"(b0), "r"(b1))
#define STS128(r0, r1, r2, r3, smem_addr) \
    asm volatile("st.shared.v4.b32 [%0], {%1, %2, %3, %4};" \
        :: "r"(smem_addr), "r"(r0), "r"(r1), "r"(r2), "r"(r3) : "memory")

// ======================= scratch globals ====================================
__device__ __align__(16) float g_agg[(size_t)N_NODES * D];   // 51.2 MB
__device__ __align__(16) float g_h[(size_t)N_NODES * D];     // 51.2 MB
__device__ int   g_cnt[N_NODES];
__device__ float g_rcnt[N_NODES];
__device__ int   g_rowptr[N_NODES];
__device__ int   g_excl[N_NODES];
__device__ int   g_cursor[N_NODES];
__device__ int   g_srcs[N_EDGES];
__device__ int   g_bsum[512];
__device__ int   g_boff[512];
__device__ __align__(16) __nv_bfloat16 g_whi[4 * 16384];     // Wl1,Wr1,Wl2,Wr2 hi
__device__ __align__(16) __nv_bfloat16 g_wlo[4 * 16384];     // lo residuals

// ======================= CSR build ==========================================
__global__ void zero_cnt_kernel() {
    int i = blockIdx.x * blockDim.x + threadIdx.x;
    if (i < N_NODES) g_cnt[i] = 0;
}
__global__ void count_kernel(const int* __restrict__ ei) {
    int e = blockIdx.x * blockDim.x + threadIdx.x;
    if (e < N_EDGES) atomicAdd(&g_cnt[ei[N_EDGES + e]], 1);
}
__global__ void rcnt_kernel() {
    int i = blockIdx.x * blockDim.x + threadIdx.x;
    if (i < N_NODES) g_rcnt[i] = 1.0f / fmaxf((float)g_cnt[i], 1.0f);
}
__global__ void scan_local_kernel() {
    __shared__ int s[256];
    int i = blockIdx.x * 256 + threadIdx.x;
    int v = (i < N_NODES) ? g_cnt[i] : 0;
    s[threadIdx.x] = v;
    __syncthreads();
#pragma unroll
    for (int off = 1; off < 256; off <<= 1) {
        int t = (threadIdx.x >= off) ? s[threadIdx.x - off] : 0;
        __syncthreads();
        s[threadIdx.x] += t;
        __syncthreads();
    }
    if (i < N_NODES) g_excl[i] = s[threadIdx.x] - v;
    if (threadIdx.x == 255) g_bsum[blockIdx.x] = s[255];
}
__global__ void scan_bsums_kernel() {
    __shared__ int s[512];
    int v = (threadIdx.x < NB) ? g_bsum[threadIdx.x] : 0;
    s[threadIdx.x] = v;
    __syncthreads();
#pragma unroll
    for (int off = 1; off < 512; off <<= 1) {
        int t = (threadIdx.x >= off) ? s[threadIdx.x - off] : 0;
        __syncthreads();
        s[threadIdx.x] += t;
        __syncthreads();
    }
    if (threadIdx.x < NB) g_boff[threadIdx.x] = s[threadIdx.x] - v;
}
__global__ void scan_add_kernel() {
    int i = blockIdx.x * 256 + threadIdx.x;
    if (i < N_NODES) {
        int r = g_excl[i] + g_boff[blockIdx.x];
        g_rowptr[i] = r;
        g_cursor[i] = r;
    }
}
__global__ void fill_src_kernel(const int* __restrict__ ei) {
    int e = blockIdx.x * blockDim.x + threadIdx.x;
    if (e < N_EDGES) {
        int d = ei[N_EDGES + e];
        int pos = atomicAdd(&g_cursor[d], 1);
        g_srcs[pos] = ei[e];
    }
}

// ======================= weight pre-split (fp32 -> bf16 hi/lo) =============
__global__ void wprep_kernel(const float* __restrict__ Wl1, const float* __restrict__ Wr1,
                             const float* __restrict__ Wl2, const float* __restrict__ Wr2) {
    int i = blockIdx.x * 256 + threadIdx.x;     // 0..65535
    int m = i >> 14, r = i & 16383;
    const float* W = (m == 0) ? Wl1 : (m == 1) ? Wr1 : (m == 2) ? Wl2 : Wr2;
    float x = W[r];
    __nv_bfloat16 h = __float2bfloat16(x);
    g_whi[i] = h;
    g_wlo[i] = __float2bfloat16(x - __bfloat162float(h));
}

// ======================= aggregation: warp-per-node CSR gather =============
template <bool FROM_GH>
__global__ __launch_bounds__(256)
void agg_kernel(const float* __restrict__ xin) {
    int node = blockIdx.x * 8 + (threadIdx.x >> 5);
    int lane = threadIdx.x & 31;
    if (node >= N_NODES) return;
    const float* x = FROM_GH ? g_h : xin;
    int beg = g_rowptr[node];
    int end = beg + g_cnt[node];

    float4 acc = make_float4(0.f, 0.f, 0.f, 0.f);
    int p = beg;
    for (; p + 1 < end; p += 2) {
        int s0 = g_srcs[p];
        int s1 = g_srcs[p + 1];
        float4 v0 = *reinterpret_cast<const float4*>(x + (size_t)s0 * D + lane * 4);
        float4 v1 = *reinterpret_cast<const float4*>(x + (size_t)s1 * D + lane * 4);
        acc.x += v0.x; acc.y += v0.y; acc.z += v0.z; acc.w += v0.w;
        acc.x += v1.x; acc.y += v1.y; acc.z += v1.z; acc.w += v1.w;
    }
    if (p < end) {
        int s0 = g_srcs[p];
        float4 v0 = *reinterpret_cast<const float4*>(x + (size_t)s0 * D + lane * 4);
        acc.x += v0.x; acc.y += v0.y; acc.z += v0.z; acc.w += v0.w;
    }
    float r = g_rcnt[node];
    acc.x *= r; acc.y *= r; acc.z *= r; acc.w *= r;
    *reinterpret_cast<float4*>(g_agg + (size_t)node * D + lane * 4) = acc;
}

// ======================= mma.sync bf16-split GEMM + bias + L2-norm =========
// out[128n x 128j] = [agg | xin] (K=256) @ [Wl | Wr]^T + bias, row-normalized.
// 8 warps: warp_m = wid&3 (32 rows), warp_n = wid>>2 (64 cols).
// 3-MMA emulated fp32: Ah*Bh + Ah*Bl + Al*Bh, fp32 accumulate.
constexpr int SROW = 40;   // smem row stride in bf16 elems (80B, conflict-free)

template <bool RELU, bool GH_IN, bool GH_OUT>
__global__ __launch_bounds__(256)
void gemm_mma_kernel(const float* __restrict__ xin_arg,
                     const float* __restrict__ bl,
                     int woff,
                     float* __restrict__ out_arg) {
    __shared__ __nv_bfloat16 sAh[128 * SROW], sAl[128 * SROW];
    __shared__ __nv_bfloat16 sBh[128 * SROW], sBl[128 * SROW];
    __shared__ float sb[128];
    __shared__ float sm_ss[2][128];

    const float* xin = GH_IN ? g_h : xin_arg;
    float*       out = GH_OUT ? g_h : out_arg;

    const int tid  = threadIdx.x;
    const int wid  = tid >> 5;
    const int lane = tid & 31;
    const int wm   = wid & 3;            // row group (32 rows)
    const int wn   = wid >> 2;           // col group (64 cols)
    const int n0   = blockIdx.x * 128;

    if (tid < 128) sb[tid] = __ldg(bl + tid);

    const uint32_t uAh = smem_u32(sAh), uAl = smem_u32(sAl);
    const uint32_t uBh = smem_u32(sBh), uBl = smem_u32(sBl);

    // global-load mapping: each thread owns (row, 16-col half)
    const int grow = tid >> 1;
    const int ghalf = tid & 1;
    const int gn   = n0 + grow;
    const int ncl  = (gn < N_NODES) ? gn : (N_NODES - 1);
    const uint32_t soff = (uint32_t)(grow * SROW + ghalf * 16) * 2;  // bytes

    float c[2][8][4];
#pragma unroll
    for (int mt = 0; mt < 2; ++mt)
#pragma unroll
        for (int nt = 0; nt < 8; ++nt)
#pragma unroll
            for (int q = 0; q < 4; ++q) c[mt][nt][q] = 0.f;

#pragma unroll 1
    for (int kt = 0; kt < 8; ++kt) {
        const float* Asrc = (kt < 4) ? g_agg : xin;
        const int gk = (kt & 3) * 32;
        __syncthreads();   // previous step's compute done before overwrite

        // ---- A: 16 fp32 -> hi/lo bf16 pairs -> smem ----
        {
            const float* ap = Asrc + (size_t)ncl * D + gk + ghalf * 16;
            float v[16];
#pragma unroll
            for (int j = 0; j < 4; ++j)
                *reinterpret_cast<float4*>(v + 4 * j) =
                    *reinterpret_cast<const float4*>(ap + 4 * j);
            uint32_t hw[8], lw[8];
#pragma unroll
            for (int j = 0; j < 8; ++j) {
                float a = v[2 * j], b = v[2 * j + 1];
                __nv_bfloat16 ha = __float2bfloat16(a);
                __nv_bfloat16 hb = __float2bfloat16(b);
                __nv_bfloat16 la = __float2bfloat16(a - __bfloat162float(ha));
                __nv_bfloat16 lb = __float2bfloat16(b - __bfloat162float(hb));
                hw[j] = ((uint32_t)__bfloat16_as_ushort(hb) << 16) |
                        (uint32_t)__bfloat16_as_ushort(ha);
                lw[j] = ((uint32_t)__bfloat16_as_ushort(lb) << 16) |
                        (uint32_t)__bfloat16_as_ushort(la);
            }
            STS128(hw[0], hw[1], hw[2], hw[3], uAh + soff);
            STS128(hw[4], hw[5], hw[6], hw[7], uAh + soff + 16);
            STS128(lw[0], lw[1], lw[2], lw[3], uAl + soff);
            STS128(lw[4], lw[5], lw[6], lw[7], uAl + soff + 16);
        }
        // ---- B: pre-split bf16 weights -> smem ----
        {
            const int wb = woff + ((kt >= 4) ? 16384 : 0);
            const __nv_bfloat16* bh = g_whi + wb + grow * D + gk + ghalf * 16;
            const __nv_bfloat16* bo = g_wlo + wb + grow * D + gk + ghalf * 16;
            uint4 h0 = *reinterpret_cast<const uint4*>(bh);
            uint4 h1 = *reinterpret_cast<const uint4*>(bh + 8);
            uint4 l0 = *reinterpret_cast<const uint4*>(bo);
            uint4 l1 = *reinterpret_cast<const uint4*>(bo + 8);
            STS128(h0.x, h0.y, h0.z, h0.w, uBh + soff);
            STS128(h1.x, h1.y, h1.z, h1.w, uBh + soff + 16);
            STS128(l0.x, l0.y, l0.z, l0.w, uBl + soff);
            STS128(l1.x, l1.y, l1.z, l1.w, uBl + soff + 16);
        }
        __syncthreads();

        // ---- compute: 2 k16 sub-steps ----
#pragma unroll
        for (int kk = 0; kk < 2; ++kk) {
            uint32_t ah[2][4], al[2][4];
#pragma unroll
            for (int mt = 0; mt < 2; ++mt) {
                uint32_t ar = (uint32_t)((wm * 32 + mt * 16 + (lane & 15)) * SROW
                                         + kk * 16 + (lane >> 4) * 8) * 2;
                LDSM_X4(ah[mt][0], ah[mt][1], ah[mt][2], ah[mt][3], uAh + ar);
                LDSM_X4(al[mt][0], al[mt][1], al[mt][2], al[mt][3], uAl + ar);
            }
            const int ln = lane & 15;
#pragma unroll
            for (int nt = 0; nt < 8; ++nt) {
                uint32_t br = (uint32_t)((wn * 64 + nt * 8 + (ln & 7)) * SROW
                                         + kk * 16 + (ln >> 3) * 8) * 2;
                uint32_t bh0, bh1, bl0, bl1;
                LDSM_X2(bh0, bh1, uBh + br);
                LDSM_X2(bl0, bl1, uBl + br);
#pragma unroll
                for (int mt = 0; mt < 2; ++mt) {
                    MMA_BF16(c[mt][nt], ah[mt], bh0, bh1);
                    MMA_BF16(c[mt][nt], ah[mt], bl0, bl1);
                    MMA_BF16(c[mt][nt], al[mt], bh0, bh1);
                }
            }
        }
    }

    // ---- epilogue: bias, row SS, normalize, (relu), store ----
    float ssA[2] = {0.f, 0.f}, ssB[2] = {0.f, 0.f};
#pragma unroll
    for (int mt = 0; mt < 2; ++mt)
#pragma unroll
        for (int nt = 0; nt < 8; ++nt) {
            int cb = wn * 64 + nt * 8 + 2 * (lane & 3);
            float b0 = sb[cb], b1 = sb[cb + 1];
            c[mt][nt][0] += b0; c[mt][nt][1] += b1;
            c[mt][nt][2] += b0; c[mt][nt][3] += b1;
            ssA[mt] += c[mt][nt][0] * c[mt][nt][0] + c[mt][nt][1] * c[mt][nt][1];
            ssB[mt] += c[mt][nt][2] * c[mt][nt][2] + c[mt][nt][3] * c[mt][nt][3];
        }
#pragma unroll
    for (int m = 1; m < 4; m <<= 1)
#pragma unroll
        for (int mt = 0; mt < 2; ++mt) {
            ssA[mt] += __shfl_xor_sync(0xffffffffu, ssA[mt], m);
            ssB[mt] += __shfl_xor_sync(0xffffffffu, ssB[mt], m);
        }
    if ((lane & 3) == 0) {
#pragma unroll
        for (int mt = 0; mt < 2; ++mt) {
            int rA = wm * 32 + mt * 16 + (lane >> 2);
            sm_ss[wn][rA]     = ssA[mt];
            sm_ss[wn][rA + 8] = ssB[mt];
        }
    }
    __syncthreads();

#pragma unroll
    for (int mt = 0; mt < 2; ++mt) {
        int rA = wm * 32 + mt * 16 + (lane >> 2);
        int rB = rA + 8;
        float invA = 1.0f / fmaxf(sqrtf(sm_ss[0][rA] + sm_ss[1][rA]), 1e-12f);
        float invB = 1.0f / fmaxf(sqrtf(sm_ss[0][rB] + sm_ss[1][rB]), 1e-12f);
        bool okA = (n0 + rA) < N_NODES;
        bool okB = (n0 + rB) < N_NODES;
        float* opA = out + (size_t)(n0 + rA) * D;
        float* opB = out + (size_t)(n0 + rB) * D;
#pragma unroll
        for (int nt = 0; nt < 8; ++nt) {
            int cb = wn * 64 + nt * 8 + 2 * (lane & 3);
            if (okA) {
                float2 w;
                w.x = c[mt][nt][0] * invA;
                w.y = c[mt][nt][1] * invA;
                if (RELU) { w.x = fmaxf(w.x, 0.f); w.y = fmaxf(w.y, 0.f); }
                *reinterpret_cast<float2*>(opA + cb) = w;
            }
            if (okB) {
                float2 w;
                w.x = c[mt][nt][2] * invB;
                w.y = c[mt][nt][3] * invB;
                if (RELU) { w.x = fmaxf(w.x, 0.f); w.y = fmaxf(w.y, 0.f); }
                *reinterpret_cast<float2*>(opB + cb) = w;
            }
        }
    }
}

// ======================= launch =============================================
extern "C" void kernel_launch(void* const* d_in, const int* in_sizes, int n_in,
                              void* d_out, int out_size) {
    const float* x   = (const float*)d_in[0];
    const int*   ei  = (const int*)d_in[1];     // int32 (JAX x64 disabled)
    const float* Wl1 = (const float*)d_in[2];
    const float* bl1 = (const float*)d_in[3];
    const float* Wr1 = (const float*)d_in[4];
    const float* Wl2 = (const float*)d_in[5];
    const float* bl2 = (const float*)d_in[6];
    const float* Wr2 = (const float*)d_in[7];
    float* out = (float*)d_out;

    const int eblocks = (N_EDGES + 255) / 256;   // 2500
    const int ablocks = (N_NODES + 7) / 8;       // 12500 (warp/node)
    const int gblocks = (N_NODES + 127) / 128;   // 782

    // CSR build + weight pre-split (layer-invariant)
    zero_cnt_kernel<<<NB, 256>>>();
    count_kernel<<<eblocks, 256>>>(ei);
    rcnt_kernel<<<NB, 256>>>();
    scan_local_kernel<<<NB, 256>>>();
    scan_bsums_kernel<<<1, 512>>>();
    scan_add_kernel<<<NB, 256>>>();
    fill_src_kernel<<<eblocks, 256>>>(ei);
    wprep_kernel<<<256, 256>>>(Wl1, Wr1, Wl2, Wr2);

    // Layer 1: agg(x) -> mma-gemm -> g_h (ReLU)
    agg_kernel<false><<<ablocks, 256>>>(x);
    gemm_mma_kernel<true, false, true><<<gblocks, 256>>>(x, bl1, 0, nullptr);

    // Layer 2: agg(g_h) -> mma-gemm -> out
    agg_kernel<true><<<ablocks, 256>>>(nullptr);
    gemm_mma_kernel<false, true, false><<<gblocks, 256>>>(nullptr, bl2, 32768, out);
}

// round 16
// speedup vs baseline: 2.5091x; 1.0099x over previous
#include <cuda_runtime.h>
#include <cuda_bf16.h>
#include <cstdint>

#define N_NODES 100000
#define N_EDGES 640000
#define D 128
#define NB 391   // ceil(N_NODES/256)

// ======================= PTX helpers ========================================
__device__ __forceinline__ uint32_t smem_u32(const void* p) {
    uint32_t a;
    asm("{ .reg .u64 t; cvta.to.shared.u64 t, %1; cvt.u32.u64 %0, t; }"
        : "=r"(a) : "l"(p));
    return a;
}
#define LDSM_X4(r0, r1, r2, r3, addr) \
    asm volatile("ldmatrix.sync.aligned.m8n8.x4.shared.b16 {%0,%1,%2,%3}, [%4];" \
        : "=r"(r0), "=r"(r1), "=r"(r2), "=r"(r3) : "r"(addr))
#define LDSM_X2(r0, r1, addr) \
    asm volatile("ldmatrix.sync.aligned.m8n8.x2.shared.b16 {%0,%1}, [%2];" \
        : "=r"(r0), "=r"(r1) : "r"(addr))
#define MMA_BF16(c, a, b0, b1) \
    asm volatile("mma.sync.aligned.m16n8k16.row.col.f32.bf16.bf16.f32 " \
        "{%0,%1,%2,%3},{%4,%5,%6,%7},{%8,%9},{%0,%1,%2,%3};" \
        : "+f"((c)[0]), "+f"((c)[1]), "+f"((c)[2]), "+f"((c)[3]) \
        : "r"((a)[0]), "r"((a)[1]), "r"((a)[2]), "r"((a)[3]), "r"(b0), "r"(b1))
#define STS128(r0, r1, r2, r3, smem_addr) \
    asm volatile("st.shared.v4.b32 [%0], {%1, %2, %3, %4};" \
        :: "r"(smem_addr), "r"(r0), "r"(r1), "r"(r2), "r"(r3) : "memory")

// ======================= scratch globals ====================================
__device__ __align__(16) float g_agg[(size_t)N_NODES * D];   // 51.2 MB
__device__ __align__(16) float g_h[(size_t)N_NODES * D];     // 51.2 MB
__device__ int   g_cnt[N_NODES];
__device__ float g_rcnt[N_NODES];
__device__ int   g_rowptr[N_NODES];
__device__ int   g_excl[N_NODES];
__device__ int   g_cursor[N_NODES];
__device__ int   g_srcs[N_EDGES];
__device__ int   g_bsum[512];
__device__ int   g_boff[512];
__device__ __align__(16) __nv_bfloat16 g_whi[4 * 16384];     // Wl1,Wr1,Wl2,Wr2 hi
__device__ __align__(16) __nv_bfloat16 g_wlo[4 * 16384];     // lo residuals

// ======================= CSR build ==========================================
__global__ void zero_cnt_kernel() {
    int i = blockIdx.x * blockDim.x + threadIdx.x;
    if (i < N_NODES) g_cnt[i] = 0;
}
__global__ void count_kernel(const int* __restrict__ ei) {
    int e = blockIdx.x * blockDim.x + threadIdx.x;
    if (e < N_EDGES) atomicAdd(&g_cnt[ei[N_EDGES + e]], 1);
}
__global__ void scan_local_kernel() {
    __shared__ int s[256];
    int i = blockIdx.x * 256 + threadIdx.x;
    int v = (i < N_NODES) ? g_cnt[i] : 0;
    s[threadIdx.x] = v;
    __syncthreads();
#pragma unroll
    for (int off = 1; off < 256; off <<= 1) {
        int t = (threadIdx.x >= off) ? s[threadIdx.x - off] : 0;
        __syncthreads();
        s[threadIdx.x] += t;
        __syncthreads();
    }
    if (i < N_NODES) g_excl[i] = s[threadIdx.x] - v;
    if (threadIdx.x == 255) g_bsum[blockIdx.x] = s[255];
}
__global__ void scan_bsums_kernel() {
    __shared__ int s[512];
    int v = (threadIdx.x < NB) ? g_bsum[threadIdx.x] : 0;
    s[threadIdx.x] = v;
    __syncthreads();
#pragma unroll
    for (int off = 1; off < 512; off <<= 1) {
        int t = (threadIdx.x >= off) ? s[threadIdx.x - off] : 0;
        __syncthreads();
        s[threadIdx.x] += t;
        __syncthreads();
    }
    if (threadIdx.x < NB) g_boff[threadIdx.x] = s[threadIdx.x] - v;
}
__global__ void scan_add_kernel() {      // also produces rcnt (merged)
    int i = blockIdx.x * 256 + threadIdx.x;
    if (i < N_NODES) {
        int r = g_excl[i] + g_boff[blockIdx.x];
        g_rowptr[i] = r;
        g_cursor[i] = r;
        g_rcnt[i] = 1.0f / fmaxf((float)g_cnt[i], 1.0f);
    }
}
__global__ void fill_src_kernel(const int* __restrict__ ei) {
    int e = blockIdx.x * blockDim.x + threadIdx.x;
    if (e < N_EDGES) {
        int d = ei[N_EDGES + e];
        int pos = atomicAdd(&g_cursor[d], 1);
        g_srcs[pos] = ei[e];
    }
}

// ======================= weight pre-split (fp32 -> bf16 hi/lo) =============
__global__ void wprep_kernel(const float* __restrict__ Wl1, const float* __restrict__ Wr1,
                             const float* __restrict__ Wl2, const float* __restrict__ Wr2) {
    int i = blockIdx.x * 256 + threadIdx.x;     // 0..65535
    int m = i >> 14, r = i & 16383;
    const float* W = (m == 0) ? Wl1 : (m == 1) ? Wr1 : (m == 2) ? Wl2 : Wr2;
    float x = W[r];
    __nv_bfloat16 h = __float2bfloat16(x);
    g_whi[i] = h;
    g_wlo[i] = __float2bfloat16(x - __bfloat162float(h));
}

// ======================= aggregation: warp-per-node, MLP-4 gather ==========
template <bool FROM_GH>
__global__ __launch_bounds__(256)
void agg_kernel(const float* __restrict__ xin) {
    int node = blockIdx.x * 8 + (threadIdx.x >> 5);
    int lane = threadIdx.x & 31;
    if (node >= N_NODES) return;
    const float* x = FROM_GH ? g_h : xin;
    int beg = g_rowptr[node];
    int end = beg + g_cnt[node];

    float4 acc = make_float4(0.f, 0.f, 0.f, 0.f);
    int p = beg;
    // 4-way batch: 4 independent row loads in flight per warp (MLP>=4)
    for (; p + 3 < end; p += 4) {
        int s0 = g_srcs[p];
        int s1 = g_srcs[p + 1];
        int s2 = g_srcs[p + 2];
        int s3 = g_srcs[p + 3];
        float4 v0 = *reinterpret_cast<const float4*>(x + (size_t)s0 * D + lane * 4);
        float4 v1 = *reinterpret_cast<const float4*>(x + (size_t)s1 * D + lane * 4);
        float4 v2 = *reinterpret_cast<const float4*>(x + (size_t)s2 * D + lane * 4);
        float4 v3 = *reinterpret_cast<const float4*>(x + (size_t)s3 * D + lane * 4);
        acc.x += v0.x + v1.x; acc.y += v0.y + v1.y;
        acc.z += v0.z + v1.z; acc.w += v0.w + v1.w;
        acc.x += v2.x + v3.x; acc.y += v2.y + v3.y;
        acc.z += v2.z + v3.z; acc.w += v2.w + v3.w;
    }
    if (p + 1 < end) {
        int s0 = g_srcs[p];
        int s1 = g_srcs[p + 1];
        float4 v0 = *reinterpret_cast<const float4*>(x + (size_t)s0 * D + lane * 4);
        float4 v1 = *reinterpret_cast<const float4*>(x + (size_t)s1 * D + lane * 4);
        acc.x += v0.x + v1.x; acc.y += v0.y + v1.y;
        acc.z += v0.z + v1.z; acc.w += v0.w + v1.w;
        p += 2;
    }
    if (p < end) {
        int s0 = g_srcs[p];
        float4 v0 = *reinterpret_cast<const float4*>(x + (size_t)s0 * D + lane * 4);
        acc.x += v0.x; acc.y += v0.y; acc.z += v0.z; acc.w += v0.w;
    }
    float r = g_rcnt[node];
    acc.x *= r; acc.y *= r; acc.z *= r; acc.w *= r;
    *reinterpret_cast<float4*>(g_agg + (size_t)node * D + lane * 4) = acc;
}

// ======================= mma.sync bf16-split GEMM (pipelined) ==============
// out[128n x 128j] = [agg | xin] (K=256) @ [Wl | Wr]^T + bias, row-normalized.
// 8 warps: warp_m = wid&3 (32 rows), warp_n = wid>>2 (64 cols).
// 3-MMA emulated fp32: Ah*Bh + Ah*Bl + Al*Bh. Software-pipelined k-loop.
constexpr int SROW = 40;   // smem row stride in bf16 elems (80B, conflict-free)

template <bool RELU, bool GH_IN, bool GH_OUT>
__global__ __launch_bounds__(256)
void gemm_mma_kernel(const float* __restrict__ xin_arg,
                     const float* __restrict__ bl,
                     int woff,
                     float* __restrict__ out_arg) {
    __shared__ __nv_bfloat16 sAh[128 * SROW], sAl[128 * SROW];
    __shared__ __nv_bfloat16 sBh[128 * SROW], sBl[128 * SROW];
    __shared__ float sb[128];
    __shared__ float sm_ss[2][128];

    const float* xin = GH_IN ? g_h : xin_arg;
    float*       out = GH_OUT ? g_h : out_arg;

    const int tid  = threadIdx.x;
    const int wid  = tid >> 5;
    const int lane = tid & 31;
    const int wm   = wid & 3;            // row group (32 rows)
    const int wn   = wid >> 2;           // col group (64 cols)
    const int n0   = blockIdx.x * 128;

    if (tid < 128) sb[tid] = __ldg(bl + tid);

    const uint32_t uAh = smem_u32(sAh), uAl = smem_u32(sAl);
    const uint32_t uBh = smem_u32(sBh), uBl = smem_u32(sBl);

    // global-load mapping: each thread owns (row, 16-col half)
    const int grow = tid >> 1;
    const int ghalf = tid & 1;
    const int gn   = n0 + grow;
    const int ncl  = (gn < N_NODES) ? gn : (N_NODES - 1);
    const uint32_t soff = (uint32_t)(grow * SROW + ghalf * 16) * 2;  // bytes

    float c[2][8][4];
#pragma unroll
    for (int mt = 0; mt < 2; ++mt)
#pragma unroll
        for (int nt = 0; nt < 8; ++nt)
#pragma unroll
            for (int q = 0; q < 4; ++q) c[mt][nt][q] = 0.f;

    auto load_A = [&](int kt, float* v) {
        const float* Asrc = (kt < 4) ? g_agg : xin;
        const float* ap = Asrc + (size_t)ncl * D + (kt & 3) * 32 + ghalf * 16;
#pragma unroll
        for (int j = 0; j < 4; ++j)
            *reinterpret_cast<float4*>(v + 4 * j) =
                *reinterpret_cast<const float4*>(ap + 4 * j);
    };
    auto load_B = [&](int kt, uint4* b) {
        const int wb = woff + ((kt >= 4) ? 16384 : 0);
        const int o  = grow * D + (kt & 3) * 32 + ghalf * 16;
        b[0] = *reinterpret_cast<const uint4*>(g_whi + wb + o);
        b[1] = *reinterpret_cast<const uint4*>(g_whi + wb + o + 8);
        b[2] = *reinterpret_cast<const uint4*>(g_wlo + wb + o);
        b[3] = *reinterpret_cast<const uint4*>(g_wlo + wb + o + 8);
    };

    float v[16];
    uint4 b[4];
    load_A(0, v);
    load_B(0, b);

#pragma unroll 1
    for (int kt = 0; kt < 8; ++kt) {
        // split A regs into hi/lo packed words
        uint32_t hw[8], lw[8];
#pragma unroll
        for (int j = 0; j < 8; ++j) {
            float a = v[2 * j], d = v[2 * j + 1];
            __nv_bfloat16 ha = __float2bfloat16(a);
            __nv_bfloat16 hd = __float2bfloat16(d);
            __nv_bfloat16 la = __float2bfloat16(a - __bfloat162float(ha));
            __nv_bfloat16 ld = __float2bfloat16(d - __bfloat162float(hd));
            hw[j] = ((uint32_t)__bfloat16_as_ushort(hd) << 16) |
                    (uint32_t)__bfloat16_as_ushort(ha);
            lw[j] = ((uint32_t)__bfloat16_as_ushort(ld) << 16) |
                    (uint32_t)__bfloat16_as_ushort(la);
        }
        __syncthreads();   // previous compute done before overwriting smem
        STS128(hw[0], hw[1], hw[2], hw[3], uAh + soff);
        STS128(hw[4], hw[5], hw[6], hw[7], uAh + soff + 16);
        STS128(lw[0], lw[1], lw[2], lw[3], uAl + soff);
        STS128(lw[4], lw[5], lw[6], lw[7], uAl + soff + 16);
        STS128(b[0].x, b[0].y, b[0].z, b[0].w, uBh + soff);
        STS128(b[1].x, b[1].y, b[1].z, b[1].w, uBh + soff + 16);
        STS128(b[2].x, b[2].y, b[2].z, b[2].w, uBl + soff);
        STS128(b[3].x, b[3].y, b[3].z, b[3].w, uBl + soff + 16);
        __syncthreads();

        // prefetch next k-step while tensor cores chew on this one
        if (kt < 7) {
            load_A(kt + 1, v);
            load_B(kt + 1, b);
        }

        // ---- compute: 2 k16 sub-steps ----
#pragma unroll
        for (int kk = 0; kk < 2; ++kk) {
            uint32_t ah[2][4], al[2][4];
#pragma unroll
            for (int mt = 0; mt < 2; ++mt) {
                uint32_t ar = (uint32_t)((wm * 32 + mt * 16 + (lane & 15)) * SROW
                                         + kk * 16 + (lane >> 4) * 8) * 2;
                LDSM_X4(ah[mt][0], ah[mt][1], ah[mt][2], ah[mt][3], uAh + ar);
                LDSM_X4(al[mt][0], al[mt][1], al[mt][2], al[mt][3], uAl + ar);
            }
            const int ln = lane & 15;
#pragma unroll
            for (int nt = 0; nt < 8; ++nt) {
                uint32_t br = (uint32_t)((wn * 64 + nt * 8 + (ln & 7)) * SROW
                                         + kk * 16 + (ln >> 3) * 8) * 2;
                uint32_t bh0, bh1, bl0, bl1;
                LDSM_X2(bh0, bh1, uBh + br);
                LDSM_X2(bl0, bl1, uBl + br);
#pragma unroll
                for (int mt = 0; mt < 2; ++mt) {
                    MMA_BF16(c[mt][nt], ah[mt], bh0, bh1);
                    MMA_BF16(c[mt][nt], ah[mt], bl0, bl1);
                    MMA_BF16(c[mt][nt], al[mt], bh0, bh1);
                }
            }
        }
    }

    // ---- epilogue: bias, row SS, normalize, (relu), store ----
    float ssA[2] = {0.f, 0.f}, ssB[2] = {0.f, 0.f};
#pragma unroll
    for (int mt = 0; mt < 2; ++mt)
#pragma unroll
        for (int nt = 0; nt < 8; ++nt) {
            int cb = wn * 64 + nt * 8 + 2 * (lane & 3);
            float b0 = sb[cb], b1 = sb[cb + 1];
            c[mt][nt][0] += b0; c[mt][nt][1] += b1;
            c[mt][nt][2] += b0; c[mt][nt][3] += b1;
            ssA[mt] += c[mt][nt][0] * c[mt][nt][0] + c[mt][nt][1] * c[mt][nt][1];
            ssB[mt] += c[mt][nt][2] * c[mt][nt][2] + c[mt][nt][3] * c[mt][nt][3];
        }
#pragma unroll
    for (int m = 1; m < 4; m <<= 1)
#pragma unroll
        for (int mt = 0; mt < 2; ++mt) {
            ssA[mt] += __shfl_xor_sync(0xffffffffu, ssA[mt], m);
            ssB[mt] += __shfl_xor_sync(0xffffffffu, ssB[mt], m);
        }
    if ((lane & 3) == 0) {
#pragma unroll
        for (int mt = 0; mt < 2; ++mt) {
            int rA = wm * 32 + mt * 16 + (lane >> 2);
            sm_ss[wn][rA]     = ssA[mt];
            sm_ss[wn][rA + 8] = ssB[mt];
        }
    }
    __syncthreads();

#pragma unroll
    for (int mt = 0; mt < 2; ++mt) {
        int rA = wm * 32 + mt * 16 + (lane >> 2);
        int rB = rA + 8;
        float invA = 1.0f / fmaxf(sqrtf(sm_ss[0][rA] + sm_ss[1][rA]), 1e-12f);
        float invB = 1.0f / fmaxf(sqrtf(sm_ss[0][rB] + sm_ss[1][rB]), 1e-12f);
        bool okA = (n0 + rA) < N_NODES;
        bool okB = (n0 + rB) < N_NODES;
        float* opA = out + (size_t)(n0 + rA) * D;
        float* opB = out + (size_t)(n0 + rB) * D;
#pragma unroll
        for (int nt = 0; nt < 8; ++nt) {
            int cb = wn * 64 + nt * 8 + 2 * (lane & 3);
            if (okA) {
                float2 w;
                w.x = c[mt][nt][0] * invA;
                w.y = c[mt][nt][1] * invA;
                if (RELU) { w.x = fmaxf(w.x, 0.f); w.y = fmaxf(w.y, 0.f); }
                *reinterpret_cast<float2*>(opA + cb) = w;
            }
            if (okB) {
                float2 w;
                w.x = c[mt][nt][2] * invB;
                w.y = c[mt][nt][3] * invB;
                if (RELU) { w.x = fmaxf(w.x, 0.f); w.y = fmaxf(w.y, 0.f); }
                *reinterpret_cast<float2*>(opB + cb) = w;
            }
        }
    }
}

// ======================= launch =============================================
extern "C" void kernel_launch(void* const* d_in, const int* in_sizes, int n_in,
                              void* d_out, int out_size) {
    const float* x   = (const float*)d_in[0];
    const int*   ei  = (const int*)d_in[1];     // int32 (JAX x64 disabled)
    const float* Wl1 = (const float*)d_in[2];
    const float* bl1 = (const float*)d_in[3];
    const float* Wr1 = (const float*)d_in[4];
    const float* Wl2 = (const float*)d_in[5];
    const float* bl2 = (const float*)d_in[6];
    const float* Wr2 = (const float*)d_in[7];
    float* out = (float*)d_out;

    const int eblocks = (N_EDGES + 255) / 256;   // 2500
    const int ablocks = (N_NODES + 7) / 8;       // 12500 (warp/node)
    const int gblocks = (N_NODES + 127) / 128;   // 782

    // CSR build + weight pre-split (layer-invariant)
    zero_cnt_kernel<<<NB, 256>>>();
    count_kernel<<<eblocks, 256>>>(ei);
    scan_local_kernel<<<NB, 256>>>();
    scan_bsums_kernel<<<1, 512>>>();
    scan_add_kernel<<<NB, 256>>>();
    fill_src_kernel<<<eblocks, 256>>>(ei);
    wprep_kernel<<<256, 256>>>(Wl1, Wr1, Wl2, Wr2);

    // Layer 1: agg(x) -> mma-gemm -> g_h (ReLU)
    agg_kernel<false><<<ablocks, 256>>>(x);
    gemm_mma_kernel<true, false, true><<<gblocks, 256>>>(x, bl1, 0, nullptr);

    // Layer 2: agg(g_h) -> mma-gemm -> out
    agg_kernel<true><<<ablocks, 256>>>(nullptr);
    gemm_mma_kernel<false, true, false><<<gblocks, 256>>>(nullptr, bl2, 32768, out);
}